// round 14
// baseline (speedup 1.0000x reference)
#include <cuda_runtime.h>
#include <cstdint>

#define NSUB 8192
#define OUTN 4761
#define TLEN 4096

// fp32 top-layer hidden states, row-major [n][64] (only rows < r0 used)
__device__ __align__(16) float g_h1[NSUB * 64];
// Convergence export
__device__ float g_rowA[64];   // h1[i-1]
__device__ float g_rowB[64];   // h1[i-2]
__device__ int   g_r0;         // first periodic row (NSUB if no convergence)
__device__ int   g_ipar;       // i & 1 at exit

__device__ __forceinline__ float tanh_fast(float x) {
    float y;
    asm("tanh.approx.f32 %0, %1;" : "=f"(y) : "f"(x));
    return y;
}

// ---------------------------------------------------------------------------
// Phase 1: serial recurrence; fused barrier+vote period-2 early exit.
//   warps 0-3: h0[i] = tanh(c0 + W_hh0 h0[i-1])
//   warps 4-7: h1[i-1] = tanh(c1 + W_ih1 h0[i-1] + W_hh1 h1[i-2])
// tanh.approx.f32 (abs err ~2e-5) is safe: the map is a contraction, so the
// perturbation does not accumulate; output error stays ~1e-4 abs << 1e-3 rel.
// ---------------------------------------------------------------------------
__global__ void __launch_bounds__(256, 1) rnn_phase1(
    const float* __restrict__ hidden,
    const float* __restrict__ W_hh0,
    const float* __restrict__ b_ih0,
    const float* __restrict__ b_hh0,
    const float* __restrict__ W_ih1,
    const float* __restrict__ W_hh1,
    const float* __restrict__ b_ih1,
    const float* __restrict__ b_hh1)
{
    __shared__ __align__(16) float ring0[4][64];
    __shared__ __align__(16) float ring1[4][64];

    const int tid = threadIdx.x;
    if (tid == 0) g_r0 = NSUB;
    if (tid < 64) {
        ring0[0][tid] = hidden[tid];
        ring1[0][tid] = hidden[64 + tid];
    }

    const bool g0 = (tid < 128);
    const int t = g0 ? tid : (tid - 128);
    const int o = t >> 1;
    const int half = t & 1;

    float wa[32], wb[32];
    float cb;
    if (g0) {
        const float* wrow = W_hh0 + o * 64 + half * 32;
#pragma unroll
        for (int j = 0; j < 32; ++j) wa[j] = wrow[j];
        cb = b_ih0[o] + b_hh0[o];
    } else {
        const float* wrow1 = W_ih1 + o * 64 + half * 32;
        const float* wrow2 = W_hh1 + o * 64 + half * 32;
#pragma unroll
        for (int j = 0; j < 32; ++j) { wa[j] = wrow1[j]; wb[j] = wrow2[j]; }
        cb = b_ih1[o] + b_hh1[o];
    }
    __syncthreads();

    for (int i = 1; i <= NSUB + 1; ++i) {
        int eq = 0;
        if (i >= 10) {
            eq = 1;
            if (tid < 64) {
                float d = fabsf(ring0[(i - 1) & 3][tid] - ring0[(i - 3) & 3][tid]);
                eq = (d < 1e-5f);
            } else if (tid < 128) {
                float d = fabsf(ring1[(i - 2) & 3][tid - 64] - ring1[(i - 4) & 3][tid - 64]);
                eq = (d < 1e-5f);
            }
        }
        if (g0) {
            if (i <= NSUB) {
                const float4* h = (const float4*)(ring0[(i - 1) & 3] + half * 32);
                float a0 = 0.f, a1 = 0.f, a2 = 0.f, a3 = 0.f;
#pragma unroll
                for (int j = 0; j < 8; ++j) {
                    float4 hv = h[j];
                    a0 = fmaf(wa[4 * j + 0], hv.x, a0);
                    a1 = fmaf(wa[4 * j + 1], hv.y, a1);
                    a2 = fmaf(wa[4 * j + 2], hv.z, a2);
                    a3 = fmaf(wa[4 * j + 3], hv.w, a3);
                }
                float s = (a0 + a1) + (a2 + a3);
                s += __shfl_xor_sync(0xffffffffu, s, 1);
                if (half == 0) ring0[i & 3][o] = tanh_fast(s + cb);
            }
        } else {
            if (i >= 2) {
                const float4* hp0 = (const float4*)(ring0[(i - 1) & 3] + half * 32);
                const float4* hp1 = (const float4*)(ring1[(i - 2) & 3] + half * 32);
                float a0 = 0.f, a1 = 0.f, a2 = 0.f, a3 = 0.f;
#pragma unroll
                for (int j = 0; j < 8; ++j) {
                    float4 u = hp0[j];
                    float4 v = hp1[j];
                    a0 = fmaf(wa[4 * j + 0], u.x, a0);
                    a1 = fmaf(wa[4 * j + 1], u.y, a1);
                    a2 = fmaf(wa[4 * j + 2], u.z, a2);
                    a3 = fmaf(wa[4 * j + 3], u.w, a3);
                    a0 = fmaf(wb[4 * j + 0], v.x, a0);
                    a1 = fmaf(wb[4 * j + 1], v.y, a1);
                    a2 = fmaf(wb[4 * j + 2], v.z, a2);
                    a3 = fmaf(wb[4 * j + 3], v.w, a3);
                }
                float s = (a0 + a1) + (a2 + a3);
                s += __shfl_xor_sync(0xffffffffu, s, 1);
                if (half == 0) {
                    float val = tanh_fast(s + cb);
                    ring1[(i - 1) & 3][o] = val;
                    g_h1[(i - 2) * 64 + o] = val;   // row n holds h1[n+1]
                }
            }
        }
        if (__syncthreads_and(eq)) {
            if (tid < 64) {
                g_rowA[tid] = ring1[(i - 1) & 3][tid];
                g_rowB[tid] = ring1[(i - 2) & 3][tid];
            }
            if (tid == 0) { g_r0 = i - 1; g_ipar = i & 1; }
            return;
        }
    }
}

// ---------------------------------------------------------------------------
// Emit: one kernel for head + broadcast fill.
// grid (19, 33, 2):
//  y==0  : head — rows n=2t+s, t<Tc. Exact projection (W row in registers)
//          for n<r0; rowA/rowB projection for padding rows [r0, r0p).
//  y>=1  : span-group (y-1) — register-resident broadcast fill; the 4
//          y-values of this thread's slot computed on the fly as wrapped
//          W-row dot products against the half's periodic h (smem).
// ---------------------------------------------------------------------------
#define SPANS_PER_HALF (TLEN / 4)     // 1024
#define SPAN_GROUPS    32
#define SPANS_PER_GRP  (SPANS_PER_HALF / SPAN_GROUPS)   // 32

__global__ void __launch_bounds__(256) emit_kernel(
    const float* __restrict__ W_lin,
    const float* __restrict__ b_lin,
    float* __restrict__ out)
{
    const int r0 = g_r0;
    int r0p = (r0 + 7) & ~7;
    if (r0p > NSUB) r0p = NSUB;
    const int Tc = r0p >> 1;              // multiple of 4
    const int s = blockIdx.z;
    const int ip = g_ipar;

    if (blockIdx.y == 0) {
        // ---- head: rows n = 2t+s, t < Tc ----
        const int c = blockIdx.x * 256 + threadIdx.x;
        if (c >= OUTN) return;
        const float4* wr = (const float4*)(W_lin + c * 64);
        float4 w[16];
#pragma unroll
        for (int j = 0; j < 16; ++j) w[j] = __ldg(wr + j);
        const float bc = b_lin[c];

        for (int t = 0; t < Tc; ++t) {
            const int n = 2 * t + s;
            const float* h;
            if (n < r0) h = g_h1 + n * 64;
            else        h = ((n & 1) == ip) ? g_rowA : g_rowB;
            const float4* hv = (const float4*)h;
            float a0 = bc, a1 = 0.f, a2 = 0.f, a3 = 0.f;
#pragma unroll
            for (int j = 0; j < 16; ++j) {
                float4 x = __ldg(hv + j);
                a0 = fmaf(w[j].x, x.x, a0);
                a1 = fmaf(w[j].y, x.y, a1);
                a2 = fmaf(w[j].z, x.z, a2);
                a3 = fmaf(w[j].w, x.w, a3);
            }
            out[(long)(s * TLEN + t) * OUTN + c] = (a0 + a1) + (a2 + a3);
        }
        return;
    }

    // ---- fill: span group (blockIdx.y - 1) ----
    __shared__ __align__(16) float hs[64];
    {
        const float* h = (s == ip) ? g_rowA : g_rowB;  // half's periodic vector
        if (threadIdx.x < 64) hs[threadIdx.x] = h[threadIdx.x];
    }
    __syncthreads();

    const int q = blockIdx.x * 256 + threadIdx.x;
    if (q >= OUTN) return;                // 4761 float4 slots per span

    // compute the 4 output values for floats [4q .. 4q+3] of the pattern
    float vv[4];
#pragma unroll
    for (int e = 0; e < 4; ++e) {
        int r = 4 * q + e;
        if (r >= 3 * OUTN)      r -= 3 * OUTN;
        else if (r >= 2 * OUTN) r -= 2 * OUTN;
        else if (r >= OUTN)     r -= OUTN;
        const float4* wr = (const float4*)(W_lin + r * 64);
        float a0 = b_lin[r], a1 = 0.f, a2 = 0.f, a3 = 0.f;
#pragma unroll
        for (int j = 0; j < 16; ++j) {
            float4 wv = __ldg(wr + j);
            a0 = fmaf(wv.x, hs[4 * j + 0], a0);
            a1 = fmaf(wv.y, hs[4 * j + 1], a1);
            a2 = fmaf(wv.z, hs[4 * j + 2], a2);
            a3 = fmaf(wv.w, hs[4 * j + 3], a3);
        }
        vv[e] = (a0 + a1) + (a2 + a3);
    }
    const float4 v = make_float4(vv[0], vv[1], vv[2], vv[3]);

    const int sp0 = (blockIdx.y - 1) * SPANS_PER_GRP;
    const long half_base = (long)s * TLEN * OUTN;   // divisible by 4
    float4* dst = (float4*)(out + half_base) + q;
    const long stride = OUTN;                        // float4s per span

    int j0 = 0;
    if (4 * sp0 < Tc) {
        int skip = (Tc - 4 * sp0 + 3) >> 2;          // spans covered by head
        if (skip >= SPANS_PER_GRP) return;
        j0 = skip;
    }
    float4* p = dst + (long)(sp0 + j0) * stride;
    int j = j0;
    for (; j + 4 <= SPANS_PER_GRP; j += 4) {
        __stcs(p, v);               p += stride;
        __stcs(p, v);               p += stride;
        __stcs(p, v);               p += stride;
        __stcs(p, v);               p += stride;
    }
    for (; j < SPANS_PER_GRP; ++j) { __stcs(p, v); p += stride; }
}

// ---------------------------------------------------------------------------
extern "C" void kernel_launch(void* const* d_in, const int* in_sizes, int n_in,
                              void* d_out, int out_size)
{
    (void)in_sizes; (void)n_in; (void)out_size;
    const float* hidden = (const float*)d_in[0];
    // d_in[1] = W_ih0: unused (RNN input is identically zero)
    const float* W_hh0  = (const float*)d_in[2];
    const float* b_ih0  = (const float*)d_in[3];
    const float* b_hh0  = (const float*)d_in[4];
    const float* W_ih1  = (const float*)d_in[5];
    const float* W_hh1  = (const float*)d_in[6];
    const float* b_ih1  = (const float*)d_in[7];
    const float* b_hh1  = (const float*)d_in[8];
    const float* W_lin  = (const float*)d_in[9];
    const float* b_lin  = (const float*)d_in[10];
    float* out = (float*)d_out;

    rnn_phase1<<<1, 256>>>(hidden, W_hh0, b_ih0, b_hh0,
                           W_ih1, W_hh1, b_ih1, b_hh1);

    dim3 egrid(19, SPAN_GROUPS + 1, 2);
    emit_kernel<<<egrid, 256>>>(W_lin, b_lin, out);
}

// round 17
// speedup vs baseline: 1.7424x; 1.7424x over previous
#include <cuda_runtime.h>
#include <cstdint>

#define NSUB 8192
#define OUTN 4761
#define TLEN 4096

// fp32 top-layer hidden states, row-major [n][64] (only rows < r0 used)
__device__ __align__(16) float g_h1[NSUB * 64];
// Convergence export
__device__ float g_rowA[64];   // h1[i-1]
__device__ float g_rowB[64];   // h1[i-2]
__device__ int   g_r0;         // first periodic row (NSUB if no convergence)
__device__ int   g_ipar;       // i & 1 at exit
// Projected periodic pair (+3 pad floats duplicating [0..2] for wrap-free gather)
__device__ __align__(16) float g_yA[OUTN + 3];
__device__ __align__(16) float g_yB[OUTN + 3];

__device__ __forceinline__ float tanh_fast(float x) {
    float y;
    asm("tanh.approx.f32 %0, %1;" : "=f"(y) : "f"(x));
    return y;
}

// ---------------------------------------------------------------------------
// Phase 1: serial recurrence; fused barrier+vote period-2 early exit.
// tanh.approx.f32 (abs err ~2e-5) is safe: contraction => no accumulation.
// ---------------------------------------------------------------------------
__global__ void __launch_bounds__(256, 1) rnn_phase1(
    const float* __restrict__ hidden,
    const float* __restrict__ W_hh0,
    const float* __restrict__ b_ih0,
    const float* __restrict__ b_hh0,
    const float* __restrict__ W_ih1,
    const float* __restrict__ W_hh1,
    const float* __restrict__ b_ih1,
    const float* __restrict__ b_hh1)
{
    __shared__ __align__(16) float ring0[4][64];
    __shared__ __align__(16) float ring1[4][64];

    const int tid = threadIdx.x;
    if (tid == 0) g_r0 = NSUB;
    if (tid < 64) {
        ring0[0][tid] = hidden[tid];
        ring1[0][tid] = hidden[64 + tid];
    }

    const bool g0 = (tid < 128);
    const int t = g0 ? tid : (tid - 128);
    const int o = t >> 1;
    const int half = t & 1;

    float wa[32], wb[32];
    float cb;
    if (g0) {
        const float* wrow = W_hh0 + o * 64 + half * 32;
#pragma unroll
        for (int j = 0; j < 32; ++j) wa[j] = wrow[j];
        cb = b_ih0[o] + b_hh0[o];
    } else {
        const float* wrow1 = W_ih1 + o * 64 + half * 32;
        const float* wrow2 = W_hh1 + o * 64 + half * 32;
#pragma unroll
        for (int j = 0; j < 32; ++j) { wa[j] = wrow1[j]; wb[j] = wrow2[j]; }
        cb = b_ih1[o] + b_hh1[o];
    }
    __syncthreads();

    for (int i = 1; i <= NSUB + 1; ++i) {
        int eq = 0;
        if (i >= 10) {
            eq = 1;
            if (tid < 64) {
                float d = fabsf(ring0[(i - 1) & 3][tid] - ring0[(i - 3) & 3][tid]);
                eq = (d < 1e-5f);
            } else if (tid < 128) {
                float d = fabsf(ring1[(i - 2) & 3][tid - 64] - ring1[(i - 4) & 3][tid - 64]);
                eq = (d < 1e-5f);
            }
        }
        if (g0) {
            if (i <= NSUB) {
                const float4* h = (const float4*)(ring0[(i - 1) & 3] + half * 32);
                float a0 = 0.f, a1 = 0.f, a2 = 0.f, a3 = 0.f;
#pragma unroll
                for (int j = 0; j < 8; ++j) {
                    float4 hv = h[j];
                    a0 = fmaf(wa[4 * j + 0], hv.x, a0);
                    a1 = fmaf(wa[4 * j + 1], hv.y, a1);
                    a2 = fmaf(wa[4 * j + 2], hv.z, a2);
                    a3 = fmaf(wa[4 * j + 3], hv.w, a3);
                }
                float s = (a0 + a1) + (a2 + a3);
                s += __shfl_xor_sync(0xffffffffu, s, 1);
                if (half == 0) ring0[i & 3][o] = tanh_fast(s + cb);
            }
        } else {
            if (i >= 2) {
                const float4* hp0 = (const float4*)(ring0[(i - 1) & 3] + half * 32);
                const float4* hp1 = (const float4*)(ring1[(i - 2) & 3] + half * 32);
                float a0 = 0.f, a1 = 0.f, a2 = 0.f, a3 = 0.f;
#pragma unroll
                for (int j = 0; j < 8; ++j) {
                    float4 u = hp0[j];
                    float4 v = hp1[j];
                    a0 = fmaf(wa[4 * j + 0], u.x, a0);
                    a1 = fmaf(wa[4 * j + 1], u.y, a1);
                    a2 = fmaf(wa[4 * j + 2], u.z, a2);
                    a3 = fmaf(wa[4 * j + 3], u.w, a3);
                    a0 = fmaf(wb[4 * j + 0], v.x, a0);
                    a1 = fmaf(wb[4 * j + 1], v.y, a1);
                    a2 = fmaf(wb[4 * j + 2], v.z, a2);
                    a3 = fmaf(wb[4 * j + 3], v.w, a3);
                }
                float s = (a0 + a1) + (a2 + a3);
                s += __shfl_xor_sync(0xffffffffu, s, 1);
                if (half == 0) {
                    float val = tanh_fast(s + cb);
                    ring1[(i - 1) & 3][o] = val;
                    g_h1[(i - 2) * 64 + o] = val;   // row n holds h1[n+1]
                }
            }
        }
        if (__syncthreads_and(eq)) {
            if (tid < 64) {
                g_rowA[tid] = ring1[(i - 1) & 3][tid];
                g_rowB[tid] = ring1[(i - 2) & 3][tid];
            }
            if (tid == 0) { g_r0 = i - 1; g_ipar = i & 1; }
            return;
        }
    }
}

// ---------------------------------------------------------------------------
// Project the two periodic vectors: yA = rowA@W^T+b, yB = rowB@W^T+b.
// Also writes the 3 pad duplicates.
// ---------------------------------------------------------------------------
__global__ void __launch_bounds__(256) yab_kernel(
    const float* __restrict__ W_lin,
    const float* __restrict__ b_lin)
{
    __shared__ float hA[64], hB[64];
    if (threadIdx.x < 64) hA[threadIdx.x] = g_rowA[threadIdx.x];
    else if (threadIdx.x < 128) hB[threadIdx.x - 64] = g_rowB[threadIdx.x - 64];
    __syncthreads();

    int p = blockIdx.x * 256 + threadIdx.x;
    if (p >= 2 * OUTN) return;
    int which = (p >= OUTN);
    int c = which ? (p - OUTN) : p;
    const float* h = which ? hB : hA;
    const float4* wr = (const float4*)(W_lin + c * 64);
    float acc = b_lin[c];
#pragma unroll
    for (int j = 0; j < 16; ++j) {
        float4 w = __ldg(wr + j);
        acc = fmaf(w.x, h[4 * j + 0], acc);
        acc = fmaf(w.y, h[4 * j + 1], acc);
        acc = fmaf(w.z, h[4 * j + 2], acc);
        acc = fmaf(w.w, h[4 * j + 3], acc);
    }
    if (which) {
        g_yB[c] = acc;
        if (c < 3) g_yB[OUTN + c] = acc;
    } else {
        g_yA[c] = acc;
        if (c < 3) g_yA[OUTN + c] = acc;
    }
}

// ---------------------------------------------------------------------------
// Head: rows n < r0p (r0 padded to multiple of 8). Exact projection for
// n < r0; periodic copy for [r0, r0p). Grid (19 col-chunks, 64 rows).
// ---------------------------------------------------------------------------
__global__ void __launch_bounds__(256) head_kernel(
    const float* __restrict__ W_lin,
    const float* __restrict__ b_lin,
    float* __restrict__ out)
{
    const int r0 = g_r0;
    int r0p = (r0 + 7) & ~7;
    if (r0p > NSUB) r0p = NSUB;
    const int ip = g_ipar;

    const int c = blockIdx.x * 256 + threadIdx.x;
    if (c >= OUTN) return;

    for (int n = blockIdx.y; n < r0p; n += gridDim.y) {
        long base = (long)((n & 1) * TLEN + (n >> 1)) * OUTN;
        float v;
        if (n < r0) {
            const float4* wr = (const float4*)(W_lin + c * 64);
            const float4* hv = (const float4*)(g_h1 + n * 64);
            float acc = b_lin[c];
#pragma unroll
            for (int j = 0; j < 16; ++j) {
                float4 w = __ldg(wr + j);
                float4 h = __ldg(hv + j);
                acc = fmaf(w.x, h.x, acc);
                acc = fmaf(w.y, h.y, acc);
                acc = fmaf(w.z, h.z, acc);
                acc = fmaf(w.w, h.w, acc);
            }
            v = acc;
        } else {
            v = ((n & 1) == ip) ? g_yA[c] : g_yB[c];
        }
        out[base + c] = v;
    }
}

// ---------------------------------------------------------------------------
// Broadcast-fill, register-resident values (R13, best measured: 30.6us).
// ---------------------------------------------------------------------------
#define SPANS_PER_HALF (TLEN / 4)     // 1024
#define SPAN_GROUPS    32
#define SPANS_PER_GRP  (SPANS_PER_HALF / SPAN_GROUPS)   // 32

__global__ void __launch_bounds__(256) fill_out(float* __restrict__ out)
{
    const int r0 = g_r0;
    int r0p = (r0 + 7) & ~7;
    if (r0p > NSUB) r0p = NSUB;
    const int Tc = r0p >> 1;              // head covers t < Tc (multiple of 4)

    const int q = blockIdx.x * 256 + threadIdx.x;
    if (q >= OUTN) return;                // 4761 float4 slots per span
    const int s = blockIdx.z;

    int m = 4 * q;
    if (m >= 3 * OUTN)      m -= 3 * OUTN;
    else if (m >= 2 * OUTN) m -= 2 * OUTN;
    else if (m >= OUTN)     m -= OUTN;
    const float* y = (s == g_ipar) ? g_yA : g_yB;
    const float4 v = make_float4(__ldg(y + m), __ldg(y + m + 1),
                                 __ldg(y + m + 2), __ldg(y + m + 3));

    const int sp0 = blockIdx.y * SPANS_PER_GRP;
    const long half_base = (long)s * TLEN * OUTN;   // divisible by 4
    float4* dst = (float4*)(out + half_base) + q;
    const long stride = OUTN;                        // float4s per span

    int j0 = 0;
    if (4 * sp0 < Tc) {
        int skip = (Tc - 4 * sp0 + 3) >> 2;          // spans covered by head
        if (skip >= SPANS_PER_GRP) return;
        j0 = skip;
    }
    float4* p = dst + (long)(sp0 + j0) * stride;
    int j = j0;
    for (; j + 4 <= SPANS_PER_GRP; j += 4) {
        __stcs(p, v);               p += stride;
        __stcs(p, v);               p += stride;
        __stcs(p, v);               p += stride;
        __stcs(p, v);               p += stride;
    }
    for (; j < SPANS_PER_GRP; ++j) { __stcs(p, v); p += stride; }
}

// ---------------------------------------------------------------------------
extern "C" void kernel_launch(void* const* d_in, const int* in_sizes, int n_in,
                              void* d_out, int out_size)
{
    (void)in_sizes; (void)n_in; (void)out_size;
    const float* hidden = (const float*)d_in[0];
    // d_in[1] = W_ih0: unused (RNN input is identically zero)
    const float* W_hh0  = (const float*)d_in[2];
    const float* b_ih0  = (const float*)d_in[3];
    const float* b_hh0  = (const float*)d_in[4];
    const float* W_ih1  = (const float*)d_in[5];
    const float* W_hh1  = (const float*)d_in[6];
    const float* b_ih1  = (const float*)d_in[7];
    const float* b_hh1  = (const float*)d_in[8];
    const float* W_lin  = (const float*)d_in[9];
    const float* b_lin  = (const float*)d_in[10];
    float* out = (float*)d_out;

    rnn_phase1<<<1, 256>>>(hidden, W_hh0, b_ih0, b_hh0,
                           W_ih1, W_hh1, b_ih1, b_hh1);

    yab_kernel<<<(2 * OUTN + 255) / 256, 256>>>(W_lin, b_lin);

    dim3 hgrid(19, 64);
    head_kernel<<<hgrid, 256>>>(W_lin, b_lin, out);

    dim3 fgrid(19, SPAN_GROUPS, 2);
    fill_out<<<fgrid, 256>>>(out);
}